// round 1
// baseline (speedup 1.0000x reference)
#include <cuda_runtime.h>
#include <stdint.h>

#define B 64
#define H 1024
#define S 4096
#define NOPS 8
#define TSTEPS 10

#define K1_SCHUNK 32
#define K1_NBLK (S / K1_SCHUNK)   // 128
#define K1_KC 64
#define K2_JC 8
#define K2_NBLK (H / K2_JC)       // 128
#define K2_KC 64
#define K2_K (2 * H)

typedef unsigned long long ull;

// persistent scratch (no allocations allowed)
__device__ float g_h[2][B * H];    // ping-pong h
__device__ float g_hn[2][B * H];   // ping-pong h_n = h + 0.01*noise[t]
__device__ ull   g_amax[TSTEPS * B];
__device__ int   g_allstop[TSTEPS];

__device__ __forceinline__ ull ffma2(ull a, ull b, ull c) {
    ull d;
    asm("fma.rn.f32x2 %0, %1, %2, %3;" : "=l"(d) : "l"(a), "l"(b), "l"(c));
    return d;
}

__device__ __forceinline__ unsigned f2ord(float f) {
    unsigned u = __float_as_uint(f);
    return (u & 0x80000000u) ? ~u : (u | 0x80000000u);
}

__global__ void k_init(const float* __restrict__ noise) {
    int tid = blockIdx.x * blockDim.x + threadIdx.x;
    int n = gridDim.x * blockDim.x;
    for (int i = tid; i < B * H; i += n) {
        g_h[0][i] = 0.f;
        g_hn[0][i] = 0.01f * noise[i];   // h0 = 0
    }
    for (int i = tid; i < TSTEPS * B; i += n) g_amax[i] = 0ull;
}

// -------- kernel 1: x-logits GEMM + per-row argmax, plus op-logits block ----
__global__ __launch_bounds__(256) void k_logits(
    int t,
    const float* __restrict__ Wx, const float* __restrict__ bx,
    const float* __restrict__ Wop, const float* __restrict__ bop)
{
    __shared__ float  sA[K1_KC][B + 4];        // h_n^T tile, row stride 68 (16B aligned)
    __shared__ float2 sB[K1_KC][K1_SCHUNK];    // W tile, each value duplicated (w,w)
    __shared__ int    sFlag[B];

    const int tid = threadIdx.x;
    const float* hn = g_hn[t & 1];

    if (blockIdx.x == K1_NBLK) {
        // ---- op-logits / all-stop block ----
        const int b = tid >> 2, q = tid & 3;
        float part[NOPS];
#pragma unroll
        for (int o = 0; o < NOPS; o++) part[o] = 0.f;
        const float* hb = hn + b * H + q * (H / 4);
        const float4* wp = (const float4*)(Wop + (size_t)(q * (H / 4)) * NOPS);
#pragma unroll 4
        for (int k = 0; k < H / 4; k++) {
            float a = hb[k];
            float4 w0 = wp[2 * k], w1 = wp[2 * k + 1];
            part[0] += a * w0.x; part[1] += a * w0.y;
            part[2] += a * w0.z; part[3] += a * w0.w;
            part[4] += a * w1.x; part[5] += a * w1.y;
            part[6] += a * w1.z; part[7] += a * w1.w;
        }
        float (*sOp)[4][NOPS] = (float (*)[4][NOPS])&sA[0][0];  // reuse smem (8KB)
#pragma unroll
        for (int o = 0; o < NOPS; o++) sOp[b][q][o] = part[o];
        __syncthreads();
        if (q == 0) {
            float best = 0.f; int bi = -1;
#pragma unroll
            for (int o = 0; o < NOPS; o++) {
                float v = sOp[b][0][o] + sOp[b][1][o] + sOp[b][2][o] + sOp[b][3][o] + bop[o];
                if (bi < 0 || v > best) { best = v; bi = o; }
            }
            sFlag[b] = (bi == 0) ? 1 : 0;
        }
        __syncthreads();
        if (tid == 0) {
            int all = 1;
            for (int i = 0; i < B; i++) all &= sFlag[i];
            g_allstop[t] = all;
        }
        return;
    }

    // ---- GEMM block: tile [64b x 32s], thread tile 4b x 2s (4 packed accs) ----
    const int s0 = blockIdx.x * K1_SCHUNK;
    const int sx = tid & 15;    // s-pair 0..15
    const int byy = tid >> 4;   // b-quad 0..15

    ull acc00 = 0, acc01 = 0, acc10 = 0, acc11 = 0;  // bits of (0.f,0.f)

    for (int k0 = 0; k0 < H; k0 += K1_KC) {
#pragma unroll
        for (int i = tid; i < K1_KC * B; i += 256) {
            int b = i >> 6, kk = i & 63;
            sA[kk][b] = hn[b * H + k0 + kk];
        }
#pragma unroll
        for (int i = tid; i < K1_KC * K1_SCHUNK; i += 256) {
            int kk = i >> 5, ss = i & 31;
            float w = Wx[(size_t)(k0 + kk) * S + s0 + ss];
            sB[kk][ss] = make_float2(w, w);
        }
        __syncthreads();
#pragma unroll 8
        for (int kk = 0; kk < K1_KC; kk++) {
            ulonglong2 av = *(const ulonglong2*)&sA[kk][byy * 4];    // (b0,b1),(b2,b3)
            ulonglong2 wv = *(const ulonglong2*)&sB[kk][sx * 2];     // (w0,w0),(w1,w1)
            acc00 = ffma2(av.x, wv.x, acc00);
            acc01 = ffma2(av.x, wv.y, acc01);
            acc10 = ffma2(av.y, wv.x, acc10);
            acc11 = ffma2(av.y, wv.y, acc11);
        }
        __syncthreads();
    }

    // write tile results to smem, then per-row argmax + global atomicMax
    float* sX = &sA[0][0];   // [B][K1_SCHUNK]
    {
        int bb = byy * 4, se = sx * 2, so = sx * 2 + 1;
        sX[(bb + 0) * K1_SCHUNK + se] = __uint_as_float((unsigned)acc00);
        sX[(bb + 1) * K1_SCHUNK + se] = __uint_as_float((unsigned)(acc00 >> 32));
        sX[(bb + 0) * K1_SCHUNK + so] = __uint_as_float((unsigned)acc01);
        sX[(bb + 1) * K1_SCHUNK + so] = __uint_as_float((unsigned)(acc01 >> 32));
        sX[(bb + 2) * K1_SCHUNK + se] = __uint_as_float((unsigned)acc10);
        sX[(bb + 3) * K1_SCHUNK + se] = __uint_as_float((unsigned)(acc10 >> 32));
        sX[(bb + 2) * K1_SCHUNK + so] = __uint_as_float((unsigned)acc11);
        sX[(bb + 3) * K1_SCHUNK + so] = __uint_as_float((unsigned)(acc11 >> 32));
    }
    __syncthreads();
    if (tid < B) {
        float best = 0.f; int bs = -1;
#pragma unroll 8
        for (int ss = 0; ss < K1_SCHUNK; ss++) {
            float v = sX[tid * K1_SCHUNK + ss] + bx[s0 + ss];
            if (bs < 0 || v > best) { best = v; bs = ss; }
        }
        // pack: ordered value in high 32, (~index) in low 32 -> max picks
        // highest value, lowest index on exact ties (matches jnp.argmax)
        ull pk = ((ull)f2ord(best) << 32) | (ull)(0xFFFFFFFFu - (unsigned)(s0 + bs));
        atomicMax(&g_amax[t * B + tid], pk);
    }
}

// -------- kernel 2: gather + [64 x 2048]@[2048 x 1024] + freeze + next h_n ---
__global__ __launch_bounds__(256) void k_update(
    int t,
    const float* __restrict__ s2a, const float* __restrict__ Wres,
    const float* __restrict__ bres, const float* __restrict__ noise,
    float* __restrict__ dst_final)
{
    __shared__ float  sA[K2_KC][B + 2];    // row stride 66 (8B aligned)
    __shared__ float2 sB[K2_KC][K2_JC];
    __shared__ int    sPtr[B];
    __shared__ int    sDone;

    const int tid = threadIdx.x;
    const float* h  = g_h[t & 1];
    const float* hn = g_hn[t & 1];
    float* dst = (t == TSTEPS - 1) ? dst_final : g_h[(t + 1) & 1];

    if (tid < B) {
        ull pk = g_amax[t * B + tid];
        int p = (int)(0xFFFFFFFFu - (unsigned)(pk & 0xFFFFFFFFull));
        sPtr[tid] = (p < S) ? p : (S - 1);
    }
    if (tid == B) {
        int d = 0;
        for (int i = 0; i < t; i++) d |= g_allstop[i];
        sDone = d;
    }
    __syncthreads();

    const int j0 = blockIdx.x * K2_JC;
    const int sx = tid & 7;    // j 0..7
    const int byy = tid >> 3;  // b-pair 0..31
    ull acc = 0;

    for (int k0 = 0; k0 < K2_K; k0 += K2_KC) {
#pragma unroll
        for (int i = tid; i < K2_KC * B; i += 256) {
            int b = i >> 6, kk = i & 63;
            int kg = k0 + kk;
            float a = (kg < H) ? hn[b * H + kg]
                               : s2a[((size_t)b * S + sPtr[b]) * H + (kg - H)];
            sA[kk][b] = a;
        }
#pragma unroll
        for (int i = tid; i < K2_KC * K2_JC; i += 256) {
            int kk = i >> 3, jj = i & 7;
            float w = Wres[(size_t)(k0 + kk) * H + j0 + jj];
            sB[kk][jj] = make_float2(w, w);
        }
        __syncthreads();
#pragma unroll 16
        for (int kk = 0; kk < K2_KC; kk++) {
            ull a = *(const ull*)&sA[kk][byy * 2];
            ull w = *(const ull*)&sB[kk][sx];
            acc = ffma2(a, w, acc);
        }
        __syncthreads();
    }

    const int b0 = byy * 2, j = j0 + sx;
    float o0, o1;
    if (sDone) {
        o0 = h[b0 * H + j];
        o1 = h[(b0 + 1) * H + j];
    } else {
        float bb = bres[j];
        o0 = __uint_as_float((unsigned)acc) + bb;
        o1 = __uint_as_float((unsigned)(acc >> 32)) + bb;
    }
    dst[b0 * H + j] = o0;
    dst[(b0 + 1) * H + j] = o1;
    if (t < TSTEPS - 1) {   // materialize next step's h_n (ping-ponged, race-free)
        const float* nz = noise + (size_t)(t + 1) * B * H;
        float* hnn = g_hn[(t + 1) & 1];
        hnn[b0 * H + j]       = o0 + 0.01f * nz[b0 * H + j];
        hnn[(b0 + 1) * H + j] = o1 + 0.01f * nz[(b0 + 1) * H + j];
    }
}

extern "C" void kernel_launch(void* const* d_in, const int* in_sizes, int n_in,
                              void* d_out, int out_size) {
    const float* s2a   = (const float*)d_in[0];
    const float* Wres  = (const float*)d_in[1];
    const float* bres  = (const float*)d_in[2];
    const float* Wop   = (const float*)d_in[3];
    const float* bop   = (const float*)d_in[4];
    const float* Wx    = (const float*)d_in[5];
    const float* bx    = (const float*)d_in[6];
    const float* noise = (const float*)d_in[7];
    float* out = (float*)d_out;

    k_init<<<64, 256>>>(noise);
    for (int t = 0; t < TSTEPS; t++) {
        k_logits<<<K1_NBLK + 1, 256>>>(t, Wx, bx, Wop, bop);
        k_update<<<K2_NBLK, 256>>>(t, s2a, Wres, bres, noise, out);
    }
}

// round 2
// speedup vs baseline: 2.6981x; 2.6981x over previous
#include <cuda_runtime.h>
#include <stdint.h>

#define B 64
#define H 1024
#define S 4096
#define NOPS 8
#define TSTEPS 10

typedef unsigned long long ull;

#define KC 32                 // k chunk depth

#define K1_SB 32              // s columns per block
#define K1_NS (S / K1_SB)     // 128 s-blocks
#define K1_KSPLIT 2
#define K1_KR (H / K1_KSPLIT) // 512
#define K1_NC (K1_KR / KC)    // 16 chunks

#define K2_JB 16              // j columns per block
#define K2_NJ (H / K2_JB)     // 64 j-blocks
#define K2_KSPLIT 8
#define K2_K (2 * H)
#define K2_KR (K2_K / K2_KSPLIT) // 256
#define K2_NC (K2_KR / KC)       // 8 chunks

// ---- persistent scratch (no allocations allowed) ----
__device__ float g_h[2][B * H];
__device__ float g_hn[2][B * H];
__device__ float g_px[K1_KSPLIT][B][S];   // x-logit partials
__device__ float g_pu[K2_KSPLIT][B][H];   // update partials
__device__ int   g_ptr[B];
__device__ int   g_allstop[TSTEPS];

__device__ __forceinline__ ull ffma2(ull a, ull b, ull c) {
    ull d;
    asm("fma.rn.f32x2 %0, %1, %2, %3;" : "=l"(d) : "l"(a), "l"(b), "l"(c));
    return d;
}
__device__ __forceinline__ float lo32(ull x) { return __uint_as_float((unsigned)x); }
__device__ __forceinline__ float hi32(ull x) { return __uint_as_float((unsigned)(x >> 32)); }
__device__ __forceinline__ unsigned f2ord(float f) {
    unsigned u = __float_as_uint(f);
    return (u & 0x80000000u) ? ~u : (u | 0x80000000u);
}

__global__ void k_init(const float* __restrict__ noise) {
    int tid = blockIdx.x * blockDim.x + threadIdx.x;
    int n = gridDim.x * blockDim.x;
    for (int i = tid; i < B * H; i += n) {
        g_h[0][i] = 0.f;
        g_hn[0][i] = 0.01f * noise[i];   // h0 = 0
    }
}

// ================= kernel 1: x-logits partial GEMM (+op-logits block) =======
__global__ __launch_bounds__(256) void k1_partial(
    int t, const float* __restrict__ Wx,
    const float* __restrict__ Wop, const float* __restrict__ bop)
{
    const float* __restrict__ hn = g_hn[t & 1];

    if (blockIdx.x == K1_NS * K1_KSPLIT) {
        // ---- op-logits / all-stop block ----
        __shared__ float sOp[B][4][NOPS];
        __shared__ int sFlag[B];
        const int tid = threadIdx.x;
        const int b = tid >> 2, q = tid & 3;
        float part[NOPS];
#pragma unroll
        for (int o = 0; o < NOPS; o++) part[o] = 0.f;
        const float* hb = hn + b * H + q * (H / 4);
        const float4* wp = (const float4*)(Wop + (size_t)(q * (H / 4)) * NOPS);
#pragma unroll 4
        for (int k = 0; k < H / 4; k++) {
            float a = hb[k];
            float4 w0 = wp[2 * k], w1 = wp[2 * k + 1];
            part[0] += a * w0.x; part[1] += a * w0.y;
            part[2] += a * w0.z; part[3] += a * w0.w;
            part[4] += a * w1.x; part[5] += a * w1.y;
            part[6] += a * w1.z; part[7] += a * w1.w;
        }
#pragma unroll
        for (int o = 0; o < NOPS; o++) sOp[b][q][o] = part[o];
        __syncthreads();
        if (q == 0) {
            float best = 0.f; int bi = -1;
#pragma unroll
            for (int o = 0; o < NOPS; o++) {
                float v = sOp[b][0][o] + sOp[b][1][o] + sOp[b][2][o] + sOp[b][3][o] + bop[o];
                if (bi < 0 || v > best) { best = v; bi = o; }
            }
            sFlag[b] = (bi == 0) ? 1 : 0;
        }
        __syncthreads();
        if (tid == 0) {
            int all = 1;
            for (int i = 0; i < B; i++) all &= sFlag[i];
            g_allstop[t] = all;
        }
        return;
    }

    __shared__ __align__(16) float  sA[2][KC][B + 4];
    __shared__ __align__(16) float2 sB[2][KC][K1_SB];

    const int tid = threadIdx.x;
    const int sb = blockIdx.x >> 1, kh = blockIdx.x & 1;
    const int s0 = sb * K1_SB;
    const int k0 = kh * K1_KR;
    const int sx = tid & 15, byy = tid >> 4;

    ull a00 = 0, a01 = 0, a10 = 0, a11 = 0;
    float ra[8], rb[4];

    // prologue: chunk 0
    {
        const int kbase = k0;
#pragma unroll
        for (int r = 0; r < 8; r++) { int i = tid + 256 * r; ra[r] = hn[(i >> 5) * H + kbase + (i & 31)]; }
#pragma unroll
        for (int r = 0; r < 4; r++) { int i = tid + 256 * r; rb[r] = Wx[(size_t)(kbase + (i >> 5)) * S + s0 + (i & 31)]; }
#pragma unroll
        for (int r = 0; r < 8; r++) { int i = tid + 256 * r; sA[0][i & 31][i >> 5] = ra[r]; }
#pragma unroll
        for (int r = 0; r < 4; r++) { int i = tid + 256 * r; sB[0][i >> 5][i & 31] = make_float2(rb[r], rb[r]); }
    }
    __syncthreads();

    for (int c = 0; c < K1_NC; c++) {
        const int cur = c & 1;
        if (c + 1 < K1_NC) {
            const int kbase = k0 + (c + 1) * KC;
#pragma unroll
            for (int r = 0; r < 8; r++) { int i = tid + 256 * r; ra[r] = hn[(i >> 5) * H + kbase + (i & 31)]; }
#pragma unroll
            for (int r = 0; r < 4; r++) { int i = tid + 256 * r; rb[r] = Wx[(size_t)(kbase + (i >> 5)) * S + s0 + (i & 31)]; }
        }
#pragma unroll
        for (int kk = 0; kk < KC; kk++) {
            ulonglong2 av = *reinterpret_cast<const ulonglong2*>(&sA[cur][kk][byy * 4]);
            ulonglong2 wv = *reinterpret_cast<const ulonglong2*>(&sB[cur][kk][sx * 2]);
            a00 = ffma2(av.x, wv.x, a00);
            a01 = ffma2(av.x, wv.y, a01);
            a10 = ffma2(av.y, wv.x, a10);
            a11 = ffma2(av.y, wv.y, a11);
        }
        if (c + 1 < K1_NC) {
            const int nxt = (c + 1) & 1;
#pragma unroll
            for (int r = 0; r < 8; r++) { int i = tid + 256 * r; sA[nxt][i & 31][i >> 5] = ra[r]; }
#pragma unroll
            for (int r = 0; r < 4; r++) { int i = tid + 256 * r; sB[nxt][i >> 5][i & 31] = make_float2(rb[r], rb[r]); }
            __syncthreads();
        }
    }

    // epilogue: partial tile -> gmem (coalesced float2 per b-row)
    const int b0 = byy * 4;
    const int se = s0 + sx * 2;
    *(float2*)&g_px[kh][b0 + 0][se] = make_float2(lo32(a00), lo32(a01));
    *(float2*)&g_px[kh][b0 + 1][se] = make_float2(hi32(a00), hi32(a01));
    *(float2*)&g_px[kh][b0 + 2][se] = make_float2(lo32(a10), lo32(a11));
    *(float2*)&g_px[kh][b0 + 3][se] = make_float2(hi32(a10), hi32(a11));
}

// ================= kernel 1b: combine K-partials + bias + row argmax ========
__global__ __launch_bounds__(128) void k1_argmax(const float* __restrict__ bx)
{
    __shared__ ull sk[128];
    const int b = blockIdx.x, tid = threadIdx.x;
    float best = __int_as_float(0xff800000);  // -inf
    int bi = 0;
    for (int s = tid; s < S; s += 128) {
        float v = g_px[0][b][s] + g_px[1][b][s] + bx[s];
        if (v > best) { best = v; bi = s; }   // strict > keeps lowest index
    }
    sk[tid] = ((ull)f2ord(best) << 32) | (ull)(0xFFFFFFFFu - (unsigned)bi);
    __syncthreads();
    for (int off = 64; off; off >>= 1) {
        if (tid < off) { ull o = sk[tid + off]; if (o > sk[tid]) sk[tid] = o; }
        __syncthreads();
    }
    if (tid == 0) {
        int p = (int)(0xFFFFFFFFu - (unsigned)(sk[0] & 0xFFFFFFFFull));
        g_ptr[b] = (p < S) ? p : (S - 1);
    }
}

// ================= kernel 2: update partial GEMM (with gather) ==============
__global__ __launch_bounds__(128) void k2_partial(
    int t, const float* __restrict__ s2a, const float* __restrict__ Wres)
{
    __shared__ __align__(16) float  sA[2][KC][B + 4];
    __shared__ __align__(16) float2 sB[2][KC][K2_JB];
    __shared__ int sPtr[B];

    const int tid = threadIdx.x;
    const int jb = blockIdx.x >> 3, ks = blockIdx.x & 7;
    const int j0 = jb * K2_JB;
    const int k0 = ks * K2_KR;
    const int sx = tid & 7, byy = tid >> 3;
    const float* __restrict__ hn = g_hn[t & 1];
    const bool gat = (k0 >= H);

    if (tid < B) sPtr[tid] = g_ptr[tid];
    __syncthreads();

    ull a00 = 0, a01 = 0, a10 = 0, a11 = 0;
    float ra[16], rb[4];

    // prologue chunk 0
    {
        const int kbase = k0;
#pragma unroll
        for (int r = 0; r < 16; r++) {
            int i = tid + 128 * r; int b = i >> 5, kg = kbase + (i & 31);
            ra[r] = gat ? s2a[((size_t)b * S + sPtr[b]) * H + (kg - H)] : hn[b * H + kg];
        }
#pragma unroll
        for (int r = 0; r < 4; r++) { int i = tid + 128 * r; rb[r] = Wres[(size_t)(kbase + (i >> 4)) * H + j0 + (i & 15)]; }
#pragma unroll
        for (int r = 0; r < 16; r++) { int i = tid + 128 * r; sA[0][i & 31][i >> 5] = ra[r]; }
#pragma unroll
        for (int r = 0; r < 4; r++) { int i = tid + 128 * r; sB[0][i >> 4][i & 15] = make_float2(rb[r], rb[r]); }
    }
    __syncthreads();

    for (int c = 0; c < K2_NC; c++) {
        const int cur = c & 1;
        if (c + 1 < K2_NC) {
            const int kbase = k0 + (c + 1) * KC;
#pragma unroll
            for (int r = 0; r < 16; r++) {
                int i = tid + 128 * r; int b = i >> 5, kg = kbase + (i & 31);
                ra[r] = gat ? s2a[((size_t)b * S + sPtr[b]) * H + (kg - H)] : hn[b * H + kg];
            }
#pragma unroll
            for (int r = 0; r < 4; r++) { int i = tid + 128 * r; rb[r] = Wres[(size_t)(kbase + (i >> 4)) * H + j0 + (i & 15)]; }
        }
#pragma unroll
        for (int kk = 0; kk < KC; kk++) {
            ulonglong2 av = *reinterpret_cast<const ulonglong2*>(&sA[cur][kk][byy * 4]);
            ulonglong2 wv = *reinterpret_cast<const ulonglong2*>(&sB[cur][kk][sx * 2]);
            a00 = ffma2(av.x, wv.x, a00);
            a01 = ffma2(av.x, wv.y, a01);
            a10 = ffma2(av.y, wv.x, a10);
            a11 = ffma2(av.y, wv.y, a11);
        }
        if (c + 1 < K2_NC) {
            const int nxt = (c + 1) & 1;
#pragma unroll
            for (int r = 0; r < 16; r++) { int i = tid + 128 * r; sA[nxt][i & 31][i >> 5] = ra[r]; }
#pragma unroll
            for (int r = 0; r < 4; r++) { int i = tid + 128 * r; sB[nxt][i >> 4][i & 15] = make_float2(rb[r], rb[r]); }
            __syncthreads();
        }
    }

    const int b0 = byy * 4;
    const int je = j0 + sx * 2;
    *(float2*)&g_pu[ks][b0 + 0][je] = make_float2(lo32(a00), lo32(a01));
    *(float2*)&g_pu[ks][b0 + 1][je] = make_float2(hi32(a00), hi32(a01));
    *(float2*)&g_pu[ks][b0 + 2][je] = make_float2(lo32(a10), lo32(a11));
    *(float2*)&g_pu[ks][b0 + 3][je] = make_float2(hi32(a10), hi32(a11));
}

// ================= kernel 2b: combine partials + bias + freeze + next h_n ===
__global__ __launch_bounds__(256) void k2_finalize(
    int t, const float* __restrict__ bres, const float* __restrict__ noise,
    float* __restrict__ out)
{
    __shared__ int sDone;
    const int b = blockIdx.x, tid = threadIdx.x;
    if (tid == 0) {
        int d = 0;
        for (int i = 0; i < t; i++) d |= g_allstop[i];
        sDone = d;
    }
    __syncthreads();

    const float* __restrict__ h = g_h[t & 1];
    float* __restrict__ dsth = (t == TSTEPS - 1) ? out : g_h[(t + 1) & 1];
    const int j = tid * 4;

    float4 v;
    if (sDone) {
        v = *(const float4*)&h[b * H + j];
    } else {
        float4 acc = make_float4(0.f, 0.f, 0.f, 0.f);
#pragma unroll
        for (int ks = 0; ks < K2_KSPLIT; ks++) {
            float4 p = *(const float4*)&g_pu[ks][b][j];
            acc.x += p.x; acc.y += p.y; acc.z += p.z; acc.w += p.w;
        }
        float4 bb = *(const float4*)&bres[j];
        v = make_float4(acc.x + bb.x, acc.y + bb.y, acc.z + bb.z, acc.w + bb.w);
    }
    *(float4*)&dsth[b * H + j] = v;

    if (t < TSTEPS - 1) {
        float4 nz = *(const float4*)&noise[((size_t)(t + 1) * B + b) * H + j];
        float4 hv = make_float4(v.x + 0.01f * nz.x, v.y + 0.01f * nz.y,
                                v.z + 0.01f * nz.z, v.w + 0.01f * nz.w);
        *(float4*)&g_hn[(t + 1) & 1][b * H + j] = hv;
    }
}

extern "C" void kernel_launch(void* const* d_in, const int* in_sizes, int n_in,
                              void* d_out, int out_size) {
    const float* s2a   = (const float*)d_in[0];
    const float* Wres  = (const float*)d_in[1];
    const float* bres  = (const float*)d_in[2];
    const float* Wop   = (const float*)d_in[3];
    const float* bop   = (const float*)d_in[4];
    const float* Wx    = (const float*)d_in[5];
    const float* bx    = (const float*)d_in[6];
    const float* noise = (const float*)d_in[7];
    float* out = (float*)d_out;

    k_init<<<64, 256>>>(noise);
    for (int t = 0; t < TSTEPS; t++) {
        k1_partial<<<K1_NS * K1_KSPLIT + 1, 256>>>(t, Wx, Wop, bop);
        k1_argmax<<<B, 128>>>(bx);
        k2_partial<<<K2_NJ * K2_KSPLIT, 128>>>(t, s2a, Wres);
        k2_finalize<<<B, 256>>>(t, bres, noise, out);
    }
}

// round 3
// speedup vs baseline: 3.7625x; 1.3945x over previous
#include <cuda_runtime.h>
#include <stdint.h>

#define B 64
#define H 1024
#define S 4096
#define NOPS 8
#define TSTEPS 10

typedef unsigned long long ull;

// ---- kernel 1 (x-logits): block tile 64b x 64s, K-split 8 ----
#define K1_SB 64
#define K1_NSB (S / K1_SB)        // 64
#define K1_KSPLIT 8
#define K1_KR (H / K1_KSPLIT)     // 128
#define K1_KC 16
#define K1_NC (K1_KR / K1_KC)     // 8
#define K1_GEMM (K1_NSB * K1_KSPLIT)  // 512
#define K1_NOPB 16
#define K1_GRID (K1_GEMM + K1_NOPB)

// ---- kernel 2 (update): block tile 64b x 32j, K-split 32 ----
#define K2_JB 32
#define K2_NJB (H / K2_JB)        // 32
#define K2_KSPLIT 32
#define K2_K (2 * H)
#define K2_KR (K2_K / K2_KSPLIT)  // 64
#define K2_KC 32
#define K2_NC (K2_KR / K2_KC)     // 2
#define K2_GRID (K2_NJB * K2_KSPLIT)  // 1024

// ---- persistent scratch ----
__device__ float g_h[2][B * H];
__device__ float g_hn[2][B * H];
__device__ float g_px[K1_KSPLIT][B][S];
__device__ float g_pu[K2_KSPLIT][B][H];
__device__ int   g_ptr[B];
__device__ int   g_opflag[TSTEPS][B];

__device__ __forceinline__ ull ffma2(ull a, ull b, ull c) {
    ull d;
    asm("fma.rn.f32x2 %0, %1, %2, %3;" : "=l"(d) : "l"(a), "l"(b), "l"(c));
    return d;
}
__device__ __forceinline__ float lo32(ull x) { return __uint_as_float((unsigned)x); }
__device__ __forceinline__ float hi32(ull x) { return __uint_as_float((unsigned)(x >> 32)); }
__device__ __forceinline__ unsigned f2ord(float f) {
    unsigned u = __float_as_uint(f);
    return (u & 0x80000000u) ? ~u : (u | 0x80000000u);
}

__global__ void k_init(const float* __restrict__ noise) {
    int tid = blockIdx.x * blockDim.x + threadIdx.x;
    int n = gridDim.x * blockDim.x;
    for (int i = tid; i < B * H; i += n) {
        g_h[0][i] = 0.f;
        g_hn[0][i] = 0.01f * noise[i];
    }
}

// ============ kernel 1: x-logit partials + op-logit blocks =================
__global__ __launch_bounds__(256) void k1_partial(
    int t, const float* __restrict__ Wx,
    const float* __restrict__ Wop, const float* __restrict__ bop)
{
    const float* __restrict__ hn = g_hn[t & 1];
    const int tid = threadIdx.x;

    if (blockIdx.x >= K1_GEMM) {
        // ------- op-logits block: 4 batch rows, full K, final flags -------
        __shared__ float sOp[4][64][NOPS];
        __shared__ float sSum[4][NOPS];
        const int b0 = (blockIdx.x - K1_GEMM) * 4;
        const int lb = tid >> 6;           // 0..3
        const int seg = tid & 63;          // 0..63
        const int b = b0 + lb;
        const int kb = seg * 16;
        float part[NOPS];
#pragma unroll
        for (int o = 0; o < NOPS; o++) part[o] = 0.f;
        const float4* wp = (const float4*)(Wop + (size_t)kb * NOPS);
#pragma unroll
        for (int g = 0; g < 4; g++) {
            float4 a4 = *(const float4*)&hn[b * H + kb + g * 4];
            float av[4] = {a4.x, a4.y, a4.z, a4.w};
#pragma unroll
            for (int c = 0; c < 4; c++) {
                float4 w0 = wp[(g * 4 + c) * 2], w1 = wp[(g * 4 + c) * 2 + 1];
                float a = av[c];
                part[0] += a * w0.x; part[1] += a * w0.y;
                part[2] += a * w0.z; part[3] += a * w0.w;
                part[4] += a * w1.x; part[5] += a * w1.y;
                part[6] += a * w1.z; part[7] += a * w1.w;
            }
        }
#pragma unroll
        for (int o = 0; o < NOPS; o++) sOp[lb][seg][o] = part[o];
        __syncthreads();
        if (tid < 32) {
            int rb = tid >> 3, o = tid & 7;
            float s = 0.f;
            for (int g = 0; g < 64; g++) s += sOp[rb][g][o];
            sSum[rb][o] = s;
        }
        __syncthreads();
        if (tid < 4) {
            float best = __int_as_float(0xff800000); int bi = -1;
#pragma unroll
            for (int o = 0; o < NOPS; o++) {
                float v = sSum[tid][o] + bop[o];
                if (v > best) { best = v; bi = o; }
            }
            g_opflag[t][b0 + tid] = (bi == 0) ? 1 : 0;
        }
        return;
    }

    // ------- GEMM block -------
    __shared__ __align__(16) float  sA[2][K1_KC][B + 4];
    __shared__ __align__(16) float2 sB[2][K1_KC][K1_SB];

    const int sb = blockIdx.x >> 3, ks = blockIdx.x & 7;
    const int s0 = sb * K1_SB;
    const int k0 = ks * K1_KR;
    const int sx = tid & 15, byy = tid >> 4;
    const int fb = tid >> 2, fg = tid & 3;

    ull acc[2][4];
#pragma unroll
    for (int p = 0; p < 2; p++)
#pragma unroll
        for (int q = 0; q < 4; q++) acc[p][q] = 0ull;

    // prologue: chunk 0
    {
        float4 a4 = *(const float4*)&hn[fb * H + k0 + fg * 4];
        sA[0][fg * 4 + 0][fb] = a4.x;
        sA[0][fg * 4 + 1][fb] = a4.y;
        sA[0][fg * 4 + 2][fb] = a4.z;
        sA[0][fg * 4 + 3][fb] = a4.w;
#pragma unroll
        for (int r = 0; r < 4; r++) {
            int i = tid + 256 * r, kk = i >> 6, ss = i & 63;
            float w = Wx[(size_t)(k0 + kk) * S + s0 + ss];
            sB[0][kk][ss] = make_float2(w, w);
        }
    }
    __syncthreads();

    for (int c = 0; c < K1_NC; c++) {
        const int cur = c & 1;
        float4 pa;
        float pb[4];
        if (c + 1 < K1_NC) {
            const int kb = k0 + (c + 1) * K1_KC;
            pa = *(const float4*)&hn[fb * H + kb + fg * 4];
#pragma unroll
            for (int r = 0; r < 4; r++) {
                int i = tid + 256 * r, kk = i >> 6, ss = i & 63;
                pb[r] = Wx[(size_t)(kb + kk) * S + s0 + ss];
            }
        }
#pragma unroll
        for (int kk = 0; kk < K1_KC; kk++) {
            ulonglong2 av = *reinterpret_cast<const ulonglong2*>(&sA[cur][kk][byy * 4]);
            ulonglong2 w0 = *reinterpret_cast<const ulonglong2*>(&sB[cur][kk][sx * 4]);
            ulonglong2 w1 = *reinterpret_cast<const ulonglong2*>(&sB[cur][kk][sx * 4 + 2]);
            acc[0][0] = ffma2(av.x, w0.x, acc[0][0]);
            acc[0][1] = ffma2(av.x, w0.y, acc[0][1]);
            acc[0][2] = ffma2(av.x, w1.x, acc[0][2]);
            acc[0][3] = ffma2(av.x, w1.y, acc[0][3]);
            acc[1][0] = ffma2(av.y, w0.x, acc[1][0]);
            acc[1][1] = ffma2(av.y, w0.y, acc[1][1]);
            acc[1][2] = ffma2(av.y, w1.x, acc[1][2]);
            acc[1][3] = ffma2(av.y, w1.y, acc[1][3]);
        }
        if (c + 1 < K1_NC) {
            const int nxt = (c + 1) & 1;
            sA[nxt][fg * 4 + 0][fb] = pa.x;
            sA[nxt][fg * 4 + 1][fb] = pa.y;
            sA[nxt][fg * 4 + 2][fb] = pa.z;
            sA[nxt][fg * 4 + 3][fb] = pa.w;
#pragma unroll
            for (int r = 0; r < 4; r++) {
                int i = tid + 256 * r, kk = i >> 6, ss = i & 63;
                sB[nxt][kk][ss] = make_float2(pb[r], pb[r]);
            }
            __syncthreads();
        }
    }

    const int b0 = byy * 4, sc = s0 + sx * 4;
    *(float4*)&g_px[ks][b0 + 0][sc] = make_float4(lo32(acc[0][0]), lo32(acc[0][1]), lo32(acc[0][2]), lo32(acc[0][3]));
    *(float4*)&g_px[ks][b0 + 1][sc] = make_float4(hi32(acc[0][0]), hi32(acc[0][1]), hi32(acc[0][2]), hi32(acc[0][3]));
    *(float4*)&g_px[ks][b0 + 2][sc] = make_float4(lo32(acc[1][0]), lo32(acc[1][1]), lo32(acc[1][2]), lo32(acc[1][3]));
    *(float4*)&g_px[ks][b0 + 3][sc] = make_float4(hi32(acc[1][0]), hi32(acc[1][1]), hi32(acc[1][2]), hi32(acc[1][3]));
}

// ============ kernel 1b: combine partials + bias + argmax ==================
__global__ __launch_bounds__(256) void k1_argmax(const float* __restrict__ bx)
{
    __shared__ ull red[8];
    const int b = blockIdx.x, tid = threadIdx.x;
    float best = __int_as_float(0xff800000);
    int bi = 0;
#pragma unroll
    for (int i = 0; i < S / 256; i++) {
        int s = i * 256 + tid;
        float v = bx[s];
#pragma unroll
        for (int ks = 0; ks < K1_KSPLIT; ks++) v += g_px[ks][b][s];
        if (v > best) { best = v; bi = s; }
    }
    ull key = ((ull)f2ord(best) << 32) | (ull)(0xFFFFFFFFu - (unsigned)bi);
#pragma unroll
    for (int off = 16; off; off >>= 1) {
        ull o = __shfl_down_sync(0xFFFFFFFFu, key, off);
        if (o > key) key = o;
    }
    if ((tid & 31) == 0) red[tid >> 5] = key;
    __syncthreads();
    if (tid == 0) {
        ull k = red[0];
#pragma unroll
        for (int w = 1; w < 8; w++) if (red[w] > k) k = red[w];
        int p = (int)(0xFFFFFFFFu - (unsigned)(k & 0xFFFFFFFFull));
        g_ptr[b] = (p < S) ? p : (S - 1);
    }
}

// ============ kernel 2: update partials (with gather) ======================
__global__ __launch_bounds__(128) void k2_partial(
    int t, const float* __restrict__ s2a, const float* __restrict__ Wres)
{
    __shared__ __align__(16) float  sA[2][K2_KC][B + 4];
    __shared__ __align__(16) float2 sB[2][K2_KC][K2_JB];
    __shared__ int sPtr[B];

    const int tid = threadIdx.x;
    const int jb = blockIdx.x >> 5, ks = blockIdx.x & 31;
    const int j0 = jb * K2_JB;
    const int k0 = ks * K2_KR;
    const int jx = tid & 7, byy = tid >> 3;
    const float* __restrict__ hn = g_hn[t & 1];
    const bool gat = (k0 >= H);

    if (tid < B) sPtr[tid] = g_ptr[tid];
    __syncthreads();

    ull acc[2][4];
#pragma unroll
    for (int p = 0; p < 2; p++)
#pragma unroll
        for (int q = 0; q < 4; q++) acc[p][q] = 0ull;

    // prologue chunk 0
    {
#pragma unroll
        for (int r = 0; r < 4; r++) {
            int i = tid + 128 * r, fb = i >> 3, g = i & 7;
            int kg = k0 + g * 4;
            float4 a4 = gat
                ? *(const float4*)&s2a[((size_t)fb * S + sPtr[fb]) * H + (kg - H)]
                : *(const float4*)&hn[fb * H + kg];
            sA[0][g * 4 + 0][fb] = a4.x;
            sA[0][g * 4 + 1][fb] = a4.y;
            sA[0][g * 4 + 2][fb] = a4.z;
            sA[0][g * 4 + 3][fb] = a4.w;
        }
#pragma unroll
        for (int r = 0; r < 8; r++) {
            int i = tid + 128 * r, kk = i >> 5, jj = i & 31;
            float w = Wres[(size_t)(k0 + kk) * H + j0 + jj];
            sB[0][kk][jj] = make_float2(w, w);
        }
    }
    __syncthreads();

    for (int c = 0; c < K2_NC; c++) {
        const int cur = c & 1;
        float4 pa[4];
        float pb[8];
        if (c + 1 < K2_NC) {
            const int kb = k0 + (c + 1) * K2_KC;
#pragma unroll
            for (int r = 0; r < 4; r++) {
                int i = tid + 128 * r, fb = i >> 3, g = i & 7;
                int kg = kb + g * 4;
                pa[r] = gat
                    ? *(const float4*)&s2a[((size_t)fb * S + sPtr[fb]) * H + (kg - H)]
                    : *(const float4*)&hn[fb * H + kg];
            }
#pragma unroll
            for (int r = 0; r < 8; r++) {
                int i = tid + 128 * r, kk = i >> 5, jj = i & 31;
                pb[r] = Wres[(size_t)(kb + kk) * H + j0 + jj];
            }
        }
#pragma unroll
        for (int kk = 0; kk < K2_KC; kk++) {
            ulonglong2 av = *reinterpret_cast<const ulonglong2*>(&sA[cur][kk][byy * 4]);
            ulonglong2 w0 = *reinterpret_cast<const ulonglong2*>(&sB[cur][kk][jx * 4]);
            ulonglong2 w1 = *reinterpret_cast<const ulonglong2*>(&sB[cur][kk][jx * 4 + 2]);
            acc[0][0] = ffma2(av.x, w0.x, acc[0][0]);
            acc[0][1] = ffma2(av.x, w0.y, acc[0][1]);
            acc[0][2] = ffma2(av.x, w1.x, acc[0][2]);
            acc[0][3] = ffma2(av.x, w1.y, acc[0][3]);
            acc[1][0] = ffma2(av.y, w0.x, acc[1][0]);
            acc[1][1] = ffma2(av.y, w0.y, acc[1][1]);
            acc[1][2] = ffma2(av.y, w1.x, acc[1][2]);
            acc[1][3] = ffma2(av.y, w1.y, acc[1][3]);
        }
        if (c + 1 < K2_NC) {
            const int nxt = (c + 1) & 1;
#pragma unroll
            for (int r = 0; r < 4; r++) {
                int i = tid + 128 * r, fb = i >> 3, g = i & 7;
                sA[nxt][g * 4 + 0][fb] = pa[r].x;
                sA[nxt][g * 4 + 1][fb] = pa[r].y;
                sA[nxt][g * 4 + 2][fb] = pa[r].z;
                sA[nxt][g * 4 + 3][fb] = pa[r].w;
            }
#pragma unroll
            for (int r = 0; r < 8; r++) {
                int i = tid + 128 * r, kk = i >> 5, jj = i & 31;
                sB[nxt][kk][jj] = make_float2(pb[r], pb[r]);
            }
            __syncthreads();
        }
    }

    const int b0 = byy * 4, jc = j0 + jx * 4;
    *(float4*)&g_pu[ks][b0 + 0][jc] = make_float4(lo32(acc[0][0]), lo32(acc[0][1]), lo32(acc[0][2]), lo32(acc[0][3]));
    *(float4*)&g_pu[ks][b0 + 1][jc] = make_float4(hi32(acc[0][0]), hi32(acc[0][1]), hi32(acc[0][2]), hi32(acc[0][3]));
    *(float4*)&g_pu[ks][b0 + 2][jc] = make_float4(lo32(acc[1][0]), lo32(acc[1][1]), lo32(acc[1][2]), lo32(acc[1][3]));
    *(float4*)&g_pu[ks][b0 + 3][jc] = make_float4(hi32(acc[1][0]), hi32(acc[1][1]), hi32(acc[1][2]), hi32(acc[1][3]));
}

// ============ kernel 2b: combine + bias + freeze + next h_n ================
__global__ __launch_bounds__(256) void k2_finalize(
    int t, const float* __restrict__ bres, const float* __restrict__ noise,
    float* __restrict__ out)
{
    const int b = blockIdx.x, tid = threadIdx.x;

    int done = 0;
    for (int tp = 0; tp < t; tp++) {
        int f = (tid < B) ? g_opflag[tp][tid] : 1;
        done |= __syncthreads_and(f);
    }

    const float* __restrict__ h = g_h[t & 1];
    float* __restrict__ dsth = (t == TSTEPS - 1) ? out : g_h[(t + 1) & 1];
    const int j = tid * 4;

    float4 v;
    if (done) {
        v = *(const float4*)&h[b * H + j];
    } else {
        float4 a = make_float4(0.f, 0.f, 0.f, 0.f);
#pragma unroll
        for (int ks = 0; ks < K2_KSPLIT; ks++) {
            float4 p = *(const float4*)&g_pu[ks][b][j];
            a.x += p.x; a.y += p.y; a.z += p.z; a.w += p.w;
        }
        float4 bb = *(const float4*)&bres[j];
        v = make_float4(a.x + bb.x, a.y + bb.y, a.z + bb.z, a.w + bb.w);
    }
    *(float4*)&dsth[b * H + j] = v;

    if (t < TSTEPS - 1) {
        float4 nz = *(const float4*)&noise[((size_t)(t + 1) * B + b) * H + j];
        float4 hv = make_float4(v.x + 0.01f * nz.x, v.y + 0.01f * nz.y,
                                v.z + 0.01f * nz.z, v.w + 0.01f * nz.w);
        *(float4*)&g_hn[(t + 1) & 1][b * H + j] = hv;
    }
}

extern "C" void kernel_launch(void* const* d_in, const int* in_sizes, int n_in,
                              void* d_out, int out_size) {
    const float* s2a   = (const float*)d_in[0];
    const float* Wres  = (const float*)d_in[1];
    const float* bres  = (const float*)d_in[2];
    const float* Wop   = (const float*)d_in[3];
    const float* bop   = (const float*)d_in[4];
    const float* Wx    = (const float*)d_in[5];
    const float* bx    = (const float*)d_in[6];
    const float* noise = (const float*)d_in[7];
    float* out = (float*)d_out;

    k_init<<<64, 256>>>(noise);
    for (int t = 0; t < TSTEPS; t++) {
        k1_partial<<<K1_GRID, 256>>>(t, Wx, Wop, bop);
        k1_argmax<<<B, 256>>>(bx);
        k2_partial<<<K2_GRID, 128>>>(t, s2a, Wres);
        k2_finalize<<<B, 256>>>(t, bres, noise, out);
    }
}

// round 4
// speedup vs baseline: 7.7652x; 2.0638x over previous
#include <cuda_runtime.h>
#include <stdint.h>

#define B 64
#define H 1024
#define S 4096
#define NOPS 8
#define TSTEPS 10

typedef unsigned long long ull;

// ---- kernel A (x-logits): tile 64b x 128s, K-split 16 ----
#define K1_SB 128
#define K1_NSB (S / K1_SB)           // 32
#define K1_KSPLIT 16
#define K1_KR (H / K1_KSPLIT)        // 64
#define K1_KC 16
#define K1_NC (K1_KR / K1_KC)        // 4
#define K1_GEMM (K1_NSB * K1_KSPLIT) // 512
#define K1_NOPB 16
#define KA_GRID (K1_GEMM + K1_NOPB)

// ---- kernel B (update): tile 64b x 64j, K-split 32 ----
#define K2_JB 64
#define K2_NJB (H / K2_JB)           // 16
#define K2_KSPLIT 32
#define K2_K (2 * H)
#define K2_KR (K2_K / K2_KSPLIT)     // 64
#define K2_KC 16
#define K2_NC (K2_KR / K2_KC)        // 4
#define K2_GEMM (K2_NJB * K2_KSPLIT) // 512
#define KB_GRID (B + K2_GEMM)        // 576

// ---- persistent scratch ----
__device__ float g_hn[B * H];
__device__ float g_px[K1_KSPLIT][B][S];   // 16 MB
__device__ float g_pu[K2_KSPLIT][B][H];   // 8 MB
__device__ int   g_ptr[B];
__device__ int   g_opflag[TSTEPS][B];
__device__ int   g_done_flag[TSTEPS];
__device__ int   g_arrived;

__device__ __forceinline__ ull ffma2(ull a, ull b, ull c) {
    ull d;
    asm("fma.rn.f32x2 %0, %1, %2, %3;" : "=l"(d) : "l"(a), "l"(b), "l"(c));
    return d;
}
__device__ __forceinline__ unsigned f2ord(float f) {
    unsigned u = __float_as_uint(f);
    return (u & 0x80000000u) ? ~u : (u | 0x80000000u);
}

// ============ KF: combine pu -> h, produce h_n(t), reset step state =========
__global__ __launch_bounds__(256) void kf(
    int t, const float* __restrict__ bres, const float* __restrict__ noise)
{
    const int b = blockIdx.x, tid = threadIdx.x;
    const int j = tid * 4;

    float4 h4 = make_float4(0.f, 0.f, 0.f, 0.f);
    if (t > 0) {
#pragma unroll
        for (int ks = 0; ks < K2_KSPLIT; ks++) {
            float4 p = *(const float4*)&g_pu[ks][b][j];
            h4.x += p.x; h4.y += p.y; h4.z += p.z; h4.w += p.w;
        }
        float4 bb = *(const float4*)&bres[j];
        h4.x += bb.x; h4.y += bb.y; h4.z += bb.z; h4.w += bb.w;
    }
    float4 nz = *(const float4*)&noise[((size_t)t * B + b) * H + j];
    float4 hn = make_float4(h4.x + 0.01f * nz.x, h4.y + 0.01f * nz.y,
                            h4.z + 0.01f * nz.z, h4.w + 0.01f * nz.w);
    *(float4*)&g_hn[b * H + j] = hn;

    if (blockIdx.x == 0) {
        int dn = 0;
        for (int tp = 0; tp < t; tp++) {
            int f = (tid < B) ? g_opflag[tp][tid] : 1;
            dn |= __syncthreads_and(f);
        }
        if (tid == 0) { g_done_flag[t] = dn; g_arrived = 0; }
    }
}

// ============ KA: x-logit partial GEMM + op-logits ==========================
__global__ __launch_bounds__(256) void ka(
    int t, const float* __restrict__ Wx,
    const float* __restrict__ Wop, const float* __restrict__ bop)
{
    const int tid = threadIdx.x;
    const float* __restrict__ hn = g_hn;

    if (blockIdx.x >= K1_GEMM) {
        // ------- op-logits block: 4 batch rows, full K -------
        __shared__ float sOp[4][64][NOPS];
        __shared__ float sSum[4][NOPS];
        const int b0 = (blockIdx.x - K1_GEMM) * 4;
        const int lb = tid >> 6, seg = tid & 63;
        const int b = b0 + lb, kb = seg * 16;
        float part[NOPS];
#pragma unroll
        for (int o = 0; o < NOPS; o++) part[o] = 0.f;
        const float4* wp = (const float4*)(Wop + (size_t)kb * NOPS);
#pragma unroll
        for (int g = 0; g < 4; g++) {
            float4 a4 = *(const float4*)&hn[b * H + kb + g * 4];
            float av[4] = {a4.x, a4.y, a4.z, a4.w};
#pragma unroll
            for (int c = 0; c < 4; c++) {
                float4 w0 = wp[(g * 4 + c) * 2], w1 = wp[(g * 4 + c) * 2 + 1];
                float a = av[c];
                part[0] += a * w0.x; part[1] += a * w0.y;
                part[2] += a * w0.z; part[3] += a * w0.w;
                part[4] += a * w1.x; part[5] += a * w1.y;
                part[6] += a * w1.z; part[7] += a * w1.w;
            }
        }
#pragma unroll
        for (int o = 0; o < NOPS; o++) sOp[lb][seg][o] = part[o];
        __syncthreads();
        if (tid < 32) {
            int rb = tid >> 3, o = tid & 7;
            float s = 0.f;
            for (int g = 0; g < 64; g++) s += sOp[rb][g][o];
            sSum[rb][o] = s;
        }
        __syncthreads();
        if (tid < 4) {
            float best = __int_as_float(0xff800000); int bi = -1;
#pragma unroll
            for (int o = 0; o < NOPS; o++) {
                float v = sSum[tid][o] + bop[o];
                if (v > best) { best = v; bi = o; }
            }
            g_opflag[t][b0 + tid] = (bi == 0) ? 1 : 0;
        }
        return;
    }

    // ------- GEMM block -------
    __shared__ __align__(16) float2 sA[2][K1_KC][B];       // (h,h) dup pairs
    __shared__ __align__(16) float  sB[2][K1_KC][K1_SB];   // raw weights

    const int ks = blockIdx.x >> 5, sb = blockIdx.x & 31;
    const int s0 = sb * K1_SB, k0 = ks * K1_KR;
    const int sx = tid & 15, byy = tid >> 4;
    const int fb = tid >> 2, fg = tid & 3;     // A fill: 1 float4/thread
    const int wk = tid >> 4, wg = tid & 15;    // B fill: 2 float4/thread

    ull acc[4][4];
#pragma unroll
    for (int p = 0; p < 4; p++)
#pragma unroll
        for (int q = 0; q < 4; q++) acc[p][q] = 0ull;

    {   // fill chunk 0
        float4 a = *(const float4*)&hn[fb * H + k0 + fg * 4];
        sA[0][fg * 4 + 0][fb] = make_float2(a.x, a.x);
        sA[0][fg * 4 + 1][fb] = make_float2(a.y, a.y);
        sA[0][fg * 4 + 2][fb] = make_float2(a.z, a.z);
        sA[0][fg * 4 + 3][fb] = make_float2(a.w, a.w);
        const float* wr = Wx + (size_t)(k0 + wk) * S + s0 + wg * 8;
        *(float4*)&sB[0][wk][wg * 8]     = *(const float4*)wr;
        *(float4*)&sB[0][wk][wg * 8 + 4] = *(const float4*)(wr + 4);
    }
    __syncthreads();

    for (int c = 0; c < K1_NC; c++) {
        const int cur = c & 1;
        float4 pa, pw0, pw1;
        if (c + 1 < K1_NC) {
            const int kb = k0 + (c + 1) * K1_KC;
            pa = *(const float4*)&hn[fb * H + kb + fg * 4];
            const float* wr = Wx + (size_t)(kb + wk) * S + s0 + wg * 8;
            pw0 = *(const float4*)wr;
            pw1 = *(const float4*)(wr + 4);
        }
#pragma unroll
        for (int kk = 0; kk < K1_KC; kk++) {
            ulonglong2 a01 = *(const ulonglong2*)&sA[cur][kk][byy * 4];
            ulonglong2 a23 = *(const ulonglong2*)&sA[cur][kk][byy * 4 + 2];
            ulonglong2 w01 = *(const ulonglong2*)&sB[cur][kk][sx * 4];
            ulonglong2 w23 = *(const ulonglong2*)&sB[cur][kk][64 + sx * 4];
            acc[0][0] = ffma2(a01.x, w01.x, acc[0][0]);
            acc[0][1] = ffma2(a01.x, w01.y, acc[0][1]);
            acc[0][2] = ffma2(a01.x, w23.x, acc[0][2]);
            acc[0][3] = ffma2(a01.x, w23.y, acc[0][3]);
            acc[1][0] = ffma2(a01.y, w01.x, acc[1][0]);
            acc[1][1] = ffma2(a01.y, w01.y, acc[1][1]);
            acc[1][2] = ffma2(a01.y, w23.x, acc[1][2]);
            acc[1][3] = ffma2(a01.y, w23.y, acc[1][3]);
            acc[2][0] = ffma2(a23.x, w01.x, acc[2][0]);
            acc[2][1] = ffma2(a23.x, w01.y, acc[2][1]);
            acc[2][2] = ffma2(a23.x, w23.x, acc[2][2]);
            acc[2][3] = ffma2(a23.x, w23.y, acc[2][3]);
            acc[3][0] = ffma2(a23.y, w01.x, acc[3][0]);
            acc[3][1] = ffma2(a23.y, w01.y, acc[3][1]);
            acc[3][2] = ffma2(a23.y, w23.x, acc[3][2]);
            acc[3][3] = ffma2(a23.y, w23.y, acc[3][3]);
        }
        if (c + 1 < K1_NC) {
            const int nxt = (c + 1) & 1;
            sA[nxt][fg * 4 + 0][fb] = make_float2(pa.x, pa.x);
            sA[nxt][fg * 4 + 1][fb] = make_float2(pa.y, pa.y);
            sA[nxt][fg * 4 + 2][fb] = make_float2(pa.z, pa.z);
            sA[nxt][fg * 4 + 3][fb] = make_float2(pa.w, pa.w);
            *(float4*)&sB[nxt][wk][wg * 8]     = pw0;
            *(float4*)&sB[nxt][wk][wg * 8 + 4] = pw1;
            __syncthreads();
        }
    }

#pragma unroll
    for (int p = 0; p < 4; p++) {
        const int b = byy * 4 + p;
        *(ulonglong2*)&g_px[ks][b][s0 + sx * 4]      = make_ulonglong2(acc[p][0], acc[p][1]);
        *(ulonglong2*)&g_px[ks][b][s0 + 64 + sx * 4] = make_ulonglong2(acc[p][2], acc[p][3]);
    }
}

// ============ KB: argmax blocks + update partial GEMM (spin for gather) =====
__global__ __launch_bounds__(128) void kb(
    int t, const float* __restrict__ s2a, const float* __restrict__ Wres,
    const float* __restrict__ bx)
{
    const int tid = threadIdx.x;

    if (blockIdx.x < B) {
        // ------- argmax block -------
        __shared__ ull red[4];
        const int b = blockIdx.x;
        float best = __int_as_float(0xff800000);
        int bi = 0;
#pragma unroll
        for (int i = 0; i < S / (128 * 4); i++) {
            int s = (i * 128 + tid) * 4;
            float4 v = *(const float4*)&bx[s];
#pragma unroll
            for (int ks = 0; ks < K1_KSPLIT; ks++) {
                float4 p = *(const float4*)&g_px[ks][b][s];
                v.x += p.x; v.y += p.y; v.z += p.z; v.w += p.w;
            }
            if (v.x > best) { best = v.x; bi = s; }
            if (v.y > best) { best = v.y; bi = s + 1; }
            if (v.z > best) { best = v.z; bi = s + 2; }
            if (v.w > best) { best = v.w; bi = s + 3; }
        }
        ull key = ((ull)f2ord(best) << 32) | (ull)(0xFFFFFFFFu - (unsigned)bi);
#pragma unroll
        for (int off = 16; off; off >>= 1) {
            ull o = __shfl_down_sync(0xFFFFFFFFu, key, off);
            if (o > key) key = o;
        }
        if ((tid & 31) == 0) red[tid >> 5] = key;
        __syncthreads();
        if (tid == 0) {
            ull k = red[0];
#pragma unroll
            for (int w = 1; w < 4; w++) if (red[w] > k) k = red[w];
            int p = (int)(0xFFFFFFFFu - (unsigned)(k & 0xFFFFFFFFull));
            g_ptr[b] = (p < S) ? p : (S - 1);
            __threadfence();
            atomicAdd(&g_arrived, 1);
        }
        return;
    }

    // ------- GEMM block -------
    if (g_done_flag[t]) return;   // frozen: keep pu (h stays fixed)

    __shared__ __align__(16) float2 sA[2][K2_KC][B];
    __shared__ __align__(16) float  sB[2][K2_KC][K2_JB];
    __shared__ int sPtr[B];

    const int q = blockIdx.x - B;
    const int ks = q >> 4, jb = q & 15;
    const int k0 = ks * K2_KR, j0 = jb * K2_JB;
    const bool gat = (k0 >= H);
    const float* __restrict__ hn = g_hn;

    if (gat) {
        if (tid == 0) {
            while (atomicAdd(&g_arrived, 0) < B) __nanosleep(128);
        }
        __syncthreads();
        __threadfence();
        if (tid < B) sPtr[tid] = g_ptr[tid];
        __syncthreads();
    }

    const int fb = tid >> 1, fg = tid & 1;   // A fill: 2 float4/thread
    const int wk = tid >> 3, wg = tid & 7;   // B fill: 2 float4/thread
    const int byy = tid >> 3, jx = tid & 7;

    ull acc[4][4];
#pragma unroll
    for (int p = 0; p < 4; p++)
#pragma unroll
        for (int q2 = 0; q2 < 4; q2++) acc[p][q2] = 0ull;

    const float* arow0 = gat ? s2a + ((size_t)fb * S + (gat ? sPtr[fb] : 0)) * H + (k0 - H)
                             : hn + fb * H + k0;

    {   // fill chunk 0
        float4 a0 = *(const float4*)(arow0 + fg * 8);
        float4 a1 = *(const float4*)(arow0 + fg * 8 + 4);
        sA[0][fg * 8 + 0][fb] = make_float2(a0.x, a0.x);
        sA[0][fg * 8 + 1][fb] = make_float2(a0.y, a0.y);
        sA[0][fg * 8 + 2][fb] = make_float2(a0.z, a0.z);
        sA[0][fg * 8 + 3][fb] = make_float2(a0.w, a0.w);
        sA[0][fg * 8 + 4][fb] = make_float2(a1.x, a1.x);
        sA[0][fg * 8 + 5][fb] = make_float2(a1.y, a1.y);
        sA[0][fg * 8 + 6][fb] = make_float2(a1.z, a1.z);
        sA[0][fg * 8 + 7][fb] = make_float2(a1.w, a1.w);
        const float* wr = Wres + (size_t)(k0 + wk) * H + j0 + wg * 8;
        *(float4*)&sB[0][wk][wg * 8]     = *(const float4*)wr;
        *(float4*)&sB[0][wk][wg * 8 + 4] = *(const float4*)(wr + 4);
    }
    __syncthreads();

    for (int c = 0; c < K2_NC; c++) {
        const int cur = c & 1;
        float4 pa0, pa1, pw0, pw1;
        if (c + 1 < K2_NC) {
            const int kof = (c + 1) * K2_KC;
            pa0 = *(const float4*)(arow0 + kof + fg * 8);
            pa1 = *(const float4*)(arow0 + kof + fg * 8 + 4);
            const float* wr = Wres + (size_t)(k0 + kof + wk) * H + j0 + wg * 8;
            pw0 = *(const float4*)wr;
            pw1 = *(const float4*)(wr + 4);
        }
#pragma unroll
        for (int kk = 0; kk < K2_KC; kk++) {
            ulonglong2 a01 = *(const ulonglong2*)&sA[cur][kk][byy * 4];
            ulonglong2 a23 = *(const ulonglong2*)&sA[cur][kk][byy * 4 + 2];
            ulonglong2 w01 = *(const ulonglong2*)&sB[cur][kk][jx * 4];
            ulonglong2 w23 = *(const ulonglong2*)&sB[cur][kk][32 + jx * 4];
            acc[0][0] = ffma2(a01.x, w01.x, acc[0][0]);
            acc[0][1] = ffma2(a01.x, w01.y, acc[0][1]);
            acc[0][2] = ffma2(a01.x, w23.x, acc[0][2]);
            acc[0][3] = ffma2(a01.x, w23.y, acc[0][3]);
            acc[1][0] = ffma2(a01.y, w01.x, acc[1][0]);
            acc[1][1] = ffma2(a01.y, w01.y, acc[1][1]);
            acc[1][2] = ffma2(a01.y, w23.x, acc[1][2]);
            acc[1][3] = ffma2(a01.y, w23.y, acc[1][3]);
            acc[2][0] = ffma2(a23.x, w01.x, acc[2][0]);
            acc[2][1] = ffma2(a23.x, w01.y, acc[2][1]);
            acc[2][2] = ffma2(a23.x, w23.x, acc[2][2]);
            acc[2][3] = ffma2(a23.x, w23.y, acc[2][3]);
            acc[3][0] = ffma2(a23.y, w01.x, acc[3][0]);
            acc[3][1] = ffma2(a23.y, w01.y, acc[3][1]);
            acc[3][2] = ffma2(a23.y, w23.x, acc[3][2]);
            acc[3][3] = ffma2(a23.y, w23.y, acc[3][3]);
        }
        if (c + 1 < K2_NC) {
            const int nxt = (c + 1) & 1;
            sA[nxt][fg * 8 + 0][fb] = make_float2(pa0.x, pa0.x);
            sA[nxt][fg * 8 + 1][fb] = make_float2(pa0.y, pa0.y);
            sA[nxt][fg * 8 + 2][fb] = make_float2(pa0.z, pa0.z);
            sA[nxt][fg * 8 + 3][fb] = make_float2(pa0.w, pa0.w);
            sA[nxt][fg * 8 + 4][fb] = make_float2(pa1.x, pa1.x);
            sA[nxt][fg * 8 + 5][fb] = make_float2(pa1.y, pa1.y);
            sA[nxt][fg * 8 + 6][fb] = make_float2(pa1.z, pa1.z);
            sA[nxt][fg * 8 + 7][fb] = make_float2(pa1.w, pa1.w);
            *(float4*)&sB[nxt][wk][wg * 8]     = pw0;
            *(float4*)&sB[nxt][wk][wg * 8 + 4] = pw1;
            __syncthreads();
        }
    }

#pragma unroll
    for (int p = 0; p < 4; p++) {
        const int b = byy * 4 + p;
        *(ulonglong2*)&g_pu[ks][b][j0 + jx * 4]      = make_ulonglong2(acc[p][0], acc[p][1]);
        *(ulonglong2*)&g_pu[ks][b][j0 + 32 + jx * 4] = make_ulonglong2(acc[p][2], acc[p][3]);
    }
}

// ============ KO: final combine -> out =====================================
__global__ __launch_bounds__(256) void ko(const float* __restrict__ bres,
                                          float* __restrict__ out)
{
    const int b = blockIdx.x, tid = threadIdx.x;
    const int j = tid * 4;
    float4 a = make_float4(0.f, 0.f, 0.f, 0.f);
#pragma unroll
    for (int ks = 0; ks < K2_KSPLIT; ks++) {
        float4 p = *(const float4*)&g_pu[ks][b][j];
        a.x += p.x; a.y += p.y; a.z += p.z; a.w += p.w;
    }
    float4 bb = *(const float4*)&bres[j];
    *(float4*)&out[b * H + j] = make_float4(a.x + bb.x, a.y + bb.y,
                                            a.z + bb.z, a.w + bb.w);
}

extern "C" void kernel_launch(void* const* d_in, const int* in_sizes, int n_in,
                              void* d_out, int out_size) {
    const float* s2a   = (const float*)d_in[0];
    const float* Wres  = (const float*)d_in[1];
    const float* bres  = (const float*)d_in[2];
    const float* Wop   = (const float*)d_in[3];
    const float* bop   = (const float*)d_in[4];
    const float* Wx    = (const float*)d_in[5];
    const float* bx    = (const float*)d_in[6];
    const float* noise = (const float*)d_in[7];
    float* out = (float*)d_out;

    for (int t = 0; t < TSTEPS; t++) {
        kf<<<B, 256>>>(t, bres, noise);
        ka<<<KA_GRID, 256>>>(t, Wx, Wop, bop);
        kb<<<KB_GRID, 128>>>(t, s2a, Wres, bx);
    }
    ko<<<B, 256>>>(bres, out);
}